// round 8
// baseline (speedup 1.0000x reference)
#include <cuda_runtime.h>
#include <cuda_bf16.h>
#include <cstdint>

// ---------------------------------------------------------------------------
// B=4, C=512, C8=64, N=4096 — all GEMMs on HMMA (mma.sync bf16, fp32 accum)
// 0) convert: xb=bf16(x), Wfgb=bf16([Wf;Wg]), Whb=bf16(Wh), bias pack
// 1) fg = Wfgb@xb + bfg  (HMMA, bf16: rows 0-63 = f, 64-127 = g)
//    hv = Whb @xb + bh   (HMMA, bf16)
// 2) fT = transpose(f)
// 3) fused logits+softmax: two-sweep recompute (no fp32 logits buffer!)
//    sweep 1: online row max/sum of exp;  sweep 2: write bf16 attn
// 4) out = gamma * (hv @ attn) + x   (HMMA, fused epilogue)
// NOTE: tcgen05 unavailable (toolchain targets compute_103 w/o 'a' features).
// ---------------------------------------------------------------------------

#define BATCH 4
#define NC    512
#define NC8   64
#define NTOK  4096

__device__ __nv_bfloat16  d_xb    [(long)BATCH * NC  * NTOK];     //  16 MB
__device__ __nv_bfloat16  d_Wfgb  [(long)2 * NC8 * NC];           // 128 KB
__device__ __nv_bfloat16  d_Whb   [(long)NC * NC];                // 512 KB
__device__ float          d_bfg   [2 * NC8];
__device__ __nv_bfloat16  d_fgb   [(long)BATCH * 2 * NC8 * NTOK]; //   8 MB
__device__ __nv_bfloat16  d_fTb   [(long)BATCH * NTOK * NC8];     //   4 MB
__device__ __nv_bfloat16  d_hvb   [(long)BATCH * NC  * NTOK];     //  16 MB
__device__ __nv_bfloat16  d_attnb [(long)BATCH * NTOK * NTOK];    // 128 MB

// ===========================================================================
// small helpers
// ===========================================================================
__device__ __forceinline__ uint32_t smem_u32(const void* p) {
    uint32_t a;
    asm("{ .reg .u64 t; cvta.to.shared.u64 t, %1; cvt.u32.u64 %0, t; }"
        : "=r"(a) : "l"(p));
    return a;
}
__device__ __forceinline__ void cp16(uint32_t s, const void* g) {
    asm volatile("cp.async.cg.shared.global [%0], [%1], 16;" :: "r"(s), "l"(g));
}
__device__ __forceinline__ void ldsm_x4(uint32_t* r, uint32_t a) {
    asm volatile("ldmatrix.sync.aligned.m8n8.x4.shared.b16 {%0,%1,%2,%3}, [%4];"
                 : "=r"(r[0]), "=r"(r[1]), "=r"(r[2]), "=r"(r[3]) : "r"(a));
}
__device__ __forceinline__ void ldsm_x2_t(uint32_t* r, uint32_t a) {
    asm volatile("ldmatrix.sync.aligned.m8n8.x2.trans.shared.b16 {%0,%1}, [%2];"
                 : "=r"(r[0]), "=r"(r[1]) : "r"(a));
}
__device__ __forceinline__ void mma_bf16(float* d, const uint32_t* a, const uint32_t* b) {
    asm volatile(
        "mma.sync.aligned.m16n8k16.row.col.f32.bf16.bf16.f32 "
        "{%0,%1,%2,%3}, {%4,%5,%6,%7}, {%8,%9}, {%0,%1,%2,%3};"
        : "+f"(d[0]), "+f"(d[1]), "+f"(d[2]), "+f"(d[3])
        : "r"(a[0]), "r"(a[1]), "r"(a[2]), "r"(a[3]), "r"(b[0]), "r"(b[1]));
}
__device__ __forceinline__ float qmax4(float v) {
    v = fmaxf(v, __shfl_xor_sync(0xffffffffu, v, 1));
    v = fmaxf(v, __shfl_xor_sync(0xffffffffu, v, 2));
    return v;
}
__device__ __forceinline__ float qsum4(float v) {
    v += __shfl_xor_sync(0xffffffffu, v, 1);
    v += __shfl_xor_sync(0xffffffffu, v, 2);
    return v;
}

// ===========================================================================
// fp32 -> bf16 convert (vectorized)
// ===========================================================================
__global__ __launch_bounds__(256) void f32_to_bf16(
    const float* __restrict__ in, __nv_bfloat16* __restrict__ out, long n4)
{
    long i = (long)blockIdx.x * 256 + threadIdx.x;
    if (i >= n4) return;
    float4 v = ((const float4*)in)[i];
    __nv_bfloat162 p[2];
    p[0] = __floats2bfloat162_rn(v.x, v.y);
    p[1] = __floats2bfloat162_rn(v.z, v.w);
    ((uint2*)out)[i] = *(uint2*)p;
}

__global__ __launch_bounds__(128) void pack_bias(
    const float* __restrict__ bf, const float* __restrict__ bg,
    float* __restrict__ bfg)
{
    int t = threadIdx.x;
    bfg[t] = (t < NC8) ? bf[t] : bg[t - NC8];
}

// ===========================================================================
// bf16 64x64-tile transpose: fT[n, o] = f[o, n]   (f: 64 x 4096 per batch)
// ===========================================================================
__global__ __launch_bounds__(256) void transpose_f(
    const __nv_bfloat16* __restrict__ in, long sIn,
    __nv_bfloat16* __restrict__ outp)
{
    __shared__ __nv_bfloat16 t[64][72];
    const __nv_bfloat16* ip = in + (long)blockIdx.z * sIn;
    __nv_bfloat16* op = outp + (long)blockIdx.z * NTOK * NC8;
    const int j0 = blockIdx.x * 64;
    const int tid = threadIdx.x;

    #pragma unroll
    for (int pass = 0; pass < 4; pass++) {
        int v = tid + pass * 256;
        int r = v >> 4, c4 = v & 15;
        uint2 d = *(const uint2*)(ip + (long)r * NTOK + j0 + c4 * 4);
        *(uint2*)&t[r][c4 * 4] = d;
    }
    __syncthreads();
    #pragma unroll
    for (int pass = 0; pass < 4; pass++) {
        int v = tid + pass * 256;
        int r = v >> 4, c4 = v & 15;
        __nv_bfloat16 tmp[4];
        tmp[0] = t[c4 * 4 + 0][r];
        tmp[1] = t[c4 * 4 + 1][r];
        tmp[2] = t[c4 * 4 + 2][r];
        tmp[3] = t[c4 * 4 + 3][r];
        *(uint2*)(op + (long)(j0 + r) * NC8 + c4 * 4) = *(uint2*)tmp;
    }
}

// ===========================================================================
// Fused logits + softmax.
// Per CTA: 128 token-rows (m0) of one batch. A = fT tile (128x64, loaded once,
// fragments hoisted to registers). Two sweeps over 32 g-tiles (64x128 each,
// double-buffered cp.async):
//   sweep 1: logits tile in regs -> online row max / exp-sum (smem m/Z)
//   sweep 2: recompute tile -> attn = exp(l - m) / Z  (bf16, written direct)
// ===========================================================================

#define LS_SMEM_AF   0
#define LS_SMEM_BS   18432              // Af: 128*72*2
#define LS_SMEM_RED  (LS_SMEM_BS + 34816)   // Bs: 2*64*136*2
#define LS_SMEM_MRUN (LS_SMEM_RED + 2048)
#define LS_SMEM_ZRUN (LS_SMEM_MRUN + 512)
#define LS_SMEM_MT   (LS_SMEM_ZRUN + 512)
#define LS_SMEM_TOT  (LS_SMEM_MT + 512)     // 56832 B

__global__ __launch_bounds__(256) void logits_softmax(
    const __nv_bfloat16* __restrict__ fT,
    const __nv_bfloat16* __restrict__ gmat, long sG,
    __nv_bfloat16* __restrict__ attn)
{
    extern __shared__ char sm[];
    __nv_bfloat16 (*Af)[72]       = (__nv_bfloat16(*)[72])(sm + LS_SMEM_AF);
    __nv_bfloat16 (*Bs)[64][136]  = (__nv_bfloat16(*)[64][136])(sm + LS_SMEM_BS);
    float (*red)[4] = (float(*)[4])(sm + LS_SMEM_RED);
    float* mrun = (float*)(sm + LS_SMEM_MRUN);
    float* zrun = (float*)(sm + LS_SMEM_ZRUN);
    float* mt   = (float*)(sm + LS_SMEM_MT);

    const int b  = blockIdx.y;
    const int m0 = blockIdx.x * 128;
    fT   += (long)b * NTOK * NC8;
    gmat += (long)b * sG;
    attn += (long)b * NTOK * NTOK + (long)m0 * NTOK;

    const int tid  = threadIdx.x;
    const int wid  = tid >> 5;
    const int lane = tid & 31;
    const int wm   = (wid >> 2) * 64;
    const int wn   = (wid & 3) * 32;
    const int wcol = wid & 3;
    const int rbase = lane >> 2;
    const int cbase = (lane & 3) * 2;

    // --- prologue loads ---
    #pragma unroll
    for (int p = 0; p < 4; p++) {
        int seg = tid * 4 + p;       // 0..1023
        int r = seg >> 3, sc = seg & 7;
        cp16(smem_u32(&Af[r][sc * 8]), fT + (long)(m0 + r) * NC8 + sc * 8);
    }
    asm volatile("cp.async.commit_group;");
    #pragma unroll
    for (int p = 0; p < 4; p++) {
        int seg = tid * 4 + p;
        int r = seg >> 4, sc = seg & 15;
        cp16(smem_u32(&Bs[0][r][sc * 8]), gmat + (long)r * NTOK + sc * 8);
    }
    asm volatile("cp.async.commit_group;");

    if (tid < 128) { mrun[tid] = -1e30f; zrun[tid] = 0.f; }

    asm volatile("cp.async.wait_group 0;");
    __syncthreads();

    // --- hoist A fragments (constant across all j tiles & both sweeps) ---
    uint32_t af[4][4][4];
    #pragma unroll
    for (int kk = 0; kk < 4; kk++)
        #pragma unroll
        for (int mi = 0; mi < 4; mi++)
            ldsm_x4(af[kk][mi], smem_u32(
                &Af[wm + mi * 16 + (lane & 15)][kk * 16 + ((lane >> 4) & 1) * 8]));

    auto load_b = [&](int st, int jt) {
        const __nv_bfloat16* gp = gmat + jt * 128;
        #pragma unroll
        for (int p = 0; p < 4; p++) {
            int seg = tid * 4 + p;
            int r = seg >> 4, sc = seg & 15;
            cp16(smem_u32(&Bs[st][r][sc * 8]), gp + (long)r * NTOK + sc * 8);
        }
        asm volatile("cp.async.commit_group;");
    };
    auto compute = [&](int st, float (&acc)[4][4][4]) {
        #pragma unroll
        for (int mi = 0; mi < 4; mi++)
            #pragma unroll
            for (int ni = 0; ni < 4; ni++)
                #pragma unroll
                for (int r = 0; r < 4; r++) acc[mi][ni][r] = 0.f;
        #pragma unroll
        for (int kk = 0; kk < 4; kk++) {
            uint32_t bfr[4][2];
            #pragma unroll
            for (int ni = 0; ni < 4; ni++)
                ldsm_x2_t(bfr[ni], smem_u32(
                    &Bs[st][kk * 16 + (lane & 15)][wn + ni * 8]));
            #pragma unroll
            for (int mi = 0; mi < 4; mi++)
                #pragma unroll
                for (int ni = 0; ni < 4; ni++)
                    mma_bf16(acc[mi][ni], af[kk][mi], bfr[ni]);
        }
    };

    // ---------------- sweep 1: online row stats ----------------
    for (int jt = 0; jt < 32; jt++) {
        const int st = jt & 1;
        if (jt + 1 < 32) {
            load_b(st ^ 1, jt + 1);
            asm volatile("cp.async.wait_group 1;");
        } else {
            asm volatile("cp.async.wait_group 0;");
        }
        __syncthreads();

        float acc[4][4][4];
        compute(st, acc);

        // per-row tile max
        #pragma unroll
        for (int mi = 0; mi < 4; mi++) {
            float lo = -1e30f, hi = -1e30f;
            #pragma unroll
            for (int ni = 0; ni < 4; ni++) {
                lo = fmaxf(lo, fmaxf(acc[mi][ni][0], acc[mi][ni][1]));
                hi = fmaxf(hi, fmaxf(acc[mi][ni][2], acc[mi][ni][3]));
            }
            lo = qmax4(lo);
            hi = qmax4(hi);
            if ((lane & 3) == 0) {
                red[wm + mi * 16 + rbase][wcol]     = lo;
                red[wm + mi * 16 + 8 + rbase][wcol] = hi;
            }
        }
        __syncthreads();
        if (tid < 128) {
            float t = fmaxf(fmaxf(red[tid][0], red[tid][1]),
                            fmaxf(red[tid][2], red[tid][3]));
            mt[tid] = fmaxf(mrun[tid], t);
        }
        __syncthreads();

        // per-row exp sum vs new max
        #pragma unroll
        for (int mi = 0; mi < 4; mi++) {
            const int rlo = wm + mi * 16 + rbase, rhi = rlo + 8;
            const float mlo = mt[rlo], mhi = mt[rhi];
            float slo = 0.f, shi = 0.f;
            #pragma unroll
            for (int ni = 0; ni < 4; ni++) {
                slo += __expf(acc[mi][ni][0] - mlo) + __expf(acc[mi][ni][1] - mlo);
                shi += __expf(acc[mi][ni][2] - mhi) + __expf(acc[mi][ni][3] - mhi);
            }
            slo = qsum4(slo);
            shi = qsum4(shi);
            if ((lane & 3) == 0) {
                red[rlo][wcol] = slo;
                red[rhi][wcol] = shi;
            }
        }
        __syncthreads();
        if (tid < 128) {
            float s = red[tid][0] + red[tid][1] + red[tid][2] + red[tid][3];
            zrun[tid] = zrun[tid] * __expf(mrun[tid] - mt[tid]) + s;
            mrun[tid] = mt[tid];
        }
        __syncthreads();
    }

    if (tid < 128) zrun[tid] = 1.0f / zrun[tid];   // zrun := 1/Z
    // (sync provided by pipeline barrier below)

    // ---------------- sweep 2: recompute + write attn ----------------
    load_b(0, 0);
    for (int jt = 0; jt < 32; jt++) {
        const int st = jt & 1;
        if (jt + 1 < 32) {
            load_b(st ^ 1, jt + 1);
            asm volatile("cp.async.wait_group 1;");
        } else {
            asm volatile("cp.async.wait_group 0;");
        }
        __syncthreads();

        float acc[4][4][4];
        compute(st, acc);

        #pragma unroll
        for (int mi = 0; mi < 4; mi++) {
            const int rlo = wm + mi * 16 + rbase, rhi = rlo + 8;
            const float mlo = mrun[rlo], ilo = zrun[rlo];
            const float mhi = mrun[rhi], ihi = zrun[rhi];
            #pragma unroll
            for (int ni = 0; ni < 4; ni++) {
                const long col = (long)jt * 128 + wn + ni * 8 + cbase;
                float p0 = __expf(acc[mi][ni][0] - mlo) * ilo;
                float p1 = __expf(acc[mi][ni][1] - mlo) * ilo;
                float p2 = __expf(acc[mi][ni][2] - mhi) * ihi;
                float p3 = __expf(acc[mi][ni][3] - mhi) * ihi;
                *(__nv_bfloat162*)&attn[(long)rlo * NTOK + col] =
                    __floats2bfloat162_rn(p0, p1);
                *(__nv_bfloat162*)&attn[(long)rhi * NTOK + col] =
                    __floats2bfloat162_rn(p2, p3);
            }
        }
        __syncthreads();   // protect Bs[st] before it is refilled next iter
    }
}

// ===========================================================================
// bf16 HMMA GEMM (mma.sync.m16n8k16), 128x128x32 tiles, 256 threads.
// EPI=0: C(bf16) = acc + bias[m]
// EPI=2: C(f32)  = gamma[0]*acc + resid[m,n]
// ===========================================================================

#define APAD 8
#define BPAD 8
#define ALD  (32 + APAD)
#define BLD  (128 + BPAD)

template<int EPI>
__global__ __launch_bounds__(256) void gemm_mma(
    const __nv_bfloat16* __restrict__ A, long sA, int ldA,
    const __nv_bfloat16* __restrict__ B, long sB, int ldB,
    void*                __restrict__ Cv, long sC, int ldC,
    const float* __restrict__ bias,
    const float* __restrict__ resid, long sR,
    const float* __restrict__ gamma,
    int K)
{
    __shared__ __nv_bfloat16 As[2][128][ALD];
    __shared__ __nv_bfloat16 Bs[2][32][BLD];

    const int b  = blockIdx.z;
    const int m0 = blockIdx.y * 128;
    const int n0 = blockIdx.x * 128;

    A += (long)b * sA;
    B += (long)b * sB;

    const int tid  = threadIdx.x;
    const int wid  = tid >> 5;
    const int lane = tid & 31;
    const int wm   = (wid >> 2) * 64;
    const int wn   = (wid & 3) * 32;

    float acc[4][4][4];
    #pragma unroll
    for (int i = 0; i < 4; i++)
        #pragma unroll
        for (int j = 0; j < 4; j++)
            #pragma unroll
            for (int r = 0; r < 4; r++) acc[i][j][r] = 0.f;

    const int aseg0 = tid * 2;
    const int bseg0 = tid * 2;

    auto load_stage = [&](int st, int k0) {
        #pragma unroll
        for (int p = 0; p < 2; p++) {
            int seg = aseg0 + p;
            int r = seg >> 2, sc = seg & 3;
            cp16(smem_u32(&As[st][r][sc * 8]),
                 A + (long)(m0 + r) * ldA + k0 + sc * 8);
        }
        #pragma unroll
        for (int p = 0; p < 2; p++) {
            int seg = bseg0 + p;
            int r = seg >> 4, sc = seg & 15;
            cp16(smem_u32(&Bs[st][r][sc * 8]),
                 B + (long)(k0 + r) * ldB + n0 + sc * 8);
        }
        asm volatile("cp.async.commit_group;");
    };

    const int KT = K >> 5;
    load_stage(0, 0);

    for (int kt = 0; kt < KT; kt++) {
        const int st = kt & 1;
        if (kt + 1 < KT) {
            load_stage(st ^ 1, (kt + 1) * 32);
            asm volatile("cp.async.wait_group 1;");
        } else {
            asm volatile("cp.async.wait_group 0;");
        }
        __syncthreads();

        #pragma unroll
        for (int kk = 0; kk < 2; kk++) {
            uint32_t af[4][4];
            #pragma unroll
            for (int mi = 0; mi < 4; mi++)
                ldsm_x4(af[mi], smem_u32(
                    &As[st][wm + mi * 16 + (lane & 15)][kk * 16 + ((lane >> 4) & 1) * 8]));
            uint32_t bf[4][2];
            #pragma unroll
            for (int ni = 0; ni < 4; ni++)
                ldsm_x2_t(bf[ni], smem_u32(
                    &Bs[st][kk * 16 + (lane & 15)][wn + ni * 8]));
            #pragma unroll
            for (int mi = 0; mi < 4; mi++)
                #pragma unroll
                for (int ni = 0; ni < 4; ni++)
                    mma_bf16(acc[mi][ni], af[mi], bf[ni]);
        }
        __syncthreads();
    }

    const int rbase = lane >> 2;
    const int cbase = (lane & 3) * 2;
    if (EPI == 0) {
        __nv_bfloat16* Cb = (__nv_bfloat16*)Cv + (long)b * sC;
        #pragma unroll
        for (int mi = 0; mi < 4; mi++) {
            #pragma unroll
            for (int ni = 0; ni < 4; ni++) {
                int row = m0 + wm + mi * 16 + rbase;
                int col = n0 + wn + ni * 8 + cbase;
                float bv0 = bias[row], bv1 = bias[row + 8];
                *(__nv_bfloat162*)&Cb[(long)row * ldC + col] =
                    __floats2bfloat162_rn(acc[mi][ni][0] + bv0, acc[mi][ni][1] + bv0);
                *(__nv_bfloat162*)&Cb[(long)(row + 8) * ldC + col] =
                    __floats2bfloat162_rn(acc[mi][ni][2] + bv1, acc[mi][ni][3] + bv1);
            }
        }
    } else {
        float* Cf = (float*)Cv + (long)b * sC;
        const float* R = resid + (long)b * sR;
        const float gm = gamma[0];
        #pragma unroll
        for (int mi = 0; mi < 4; mi++) {
            #pragma unroll
            for (int ni = 0; ni < 4; ni++) {
                int row = m0 + wm + mi * 16 + rbase;
                int col = n0 + wn + ni * 8 + cbase;
                float2 r0 = *(const float2*)&R[(long)row * ldC + col];
                float2 r1 = *(const float2*)&R[(long)(row + 8) * ldC + col];
                float2 o0, o1;
                o0.x = gm * acc[mi][ni][0] + r0.x;
                o0.y = gm * acc[mi][ni][1] + r0.y;
                o1.x = gm * acc[mi][ni][2] + r1.x;
                o1.y = gm * acc[mi][ni][3] + r1.y;
                *(float2*)&Cf[(long)row * ldC + col] = o0;
                *(float2*)&Cf[(long)(row + 8) * ldC + col] = o1;
            }
        }
    }
}

// ===========================================================================
// kernel_launch  — inputs: x, Wf, bf, Wg, bg, Wh, bh, gamma
// ===========================================================================
extern "C" void kernel_launch(void* const* d_in, const int* in_sizes, int n_in,
                              void* d_out, int out_size)
{
    const float* x     = (const float*)d_in[0];
    const float* Wf    = (const float*)d_in[1];
    const float* bfp   = (const float*)d_in[2];
    const float* Wg    = (const float*)d_in[3];
    const float* bgp   = (const float*)d_in[4];
    const float* Wh    = (const float*)d_in[5];
    const float* bh    = (const float*)d_in[6];
    const float* gamma = (const float*)d_in[7];
    float* out = (float*)d_out;

    void *pxb, *pwfg, *pwh, *pbfg, *pfg, *pft, *ph, *pab;
    cudaGetSymbolAddress(&pxb,  d_xb);
    cudaGetSymbolAddress(&pwfg, d_Wfgb);
    cudaGetSymbolAddress(&pwh,  d_Whb);
    cudaGetSymbolAddress(&pbfg, d_bfg);
    cudaGetSymbolAddress(&pfg,  d_fgb);
    cudaGetSymbolAddress(&pft,  d_fTb);
    cudaGetSymbolAddress(&ph,   d_hvb);
    cudaGetSymbolAddress(&pab,  d_attnb);
    __nv_bfloat16* xb    = (__nv_bfloat16*)pxb;
    __nv_bfloat16* Wfgb  = (__nv_bfloat16*)pwfg;
    __nv_bfloat16* Whb   = (__nv_bfloat16*)pwh;
    float*         bfg   = (float*)pbfg;
    __nv_bfloat16* fgb   = (__nv_bfloat16*)pfg;
    __nv_bfloat16* fTb   = (__nv_bfloat16*)pft;
    __nv_bfloat16* hvb   = (__nv_bfloat16*)ph;
    __nv_bfloat16* attnb = (__nv_bfloat16*)pab;

    const long sx  = (long)NC * NTOK;
    const long sfg = (long)2 * NC8 * NTOK;
    const long sat = (long)NTOK * NTOK;

    static bool attr_set = false;
    if (!attr_set) {
        cudaFuncSetAttribute(logits_softmax,
                             cudaFuncAttributeMaxDynamicSharedMemorySize, LS_SMEM_TOT);
        attr_set = true;
    }

    // 0) conversions + bias pack
    {
        long n4 = (long)BATCH * NC * NTOK / 4;
        f32_to_bf16<<<(unsigned)((n4 + 255) / 256), 256>>>(x, xb, n4);
        long wfg4 = (long)NC8 * NC / 4;
        f32_to_bf16<<<(unsigned)((wfg4 + 255) / 256), 256>>>(Wf, Wfgb, wfg4);
        f32_to_bf16<<<(unsigned)((wfg4 + 255) / 256), 256>>>(Wg, Wfgb + (long)NC8 * NC, wfg4);
        long wh4 = (long)NC * NC / 4;
        f32_to_bf16<<<(unsigned)((wh4 + 255) / 256), 256>>>(Wh, Whb, wh4);
        pack_bias<<<1, 128>>>(bfp, bgp, bfg);
    }

    // 1) fg = Wfgb @ xb + bfg  (rows 0-63 = f, 64-127 = g)
    gemm_mma<0><<<dim3(NTOK / 128, 1, BATCH), 256>>>(
        Wfgb, 0, NC, xb, sx, NTOK, fgb, sfg, NTOK, bfg, nullptr, 0, nullptr, NC);

    // 1b) hv = Whb @ xb + bh
    gemm_mma<0><<<dim3(NTOK / 128, NC / 128, BATCH), 256>>>(
        Whb, 0, NC, xb, sx, NTOK, hvb, sx, NTOK, bh, nullptr, 0, nullptr, NC);

    // 2) fT = transpose(f)
    transpose_f<<<dim3(NTOK / 64, 1, BATCH), 256>>>(fgb, sfg, fTb);

    // 3+4) fused logits + softmax -> bf16 attn (no fp32 logits buffer)
    logits_softmax<<<dim3(NTOK / 128, BATCH), 256, LS_SMEM_TOT>>>(
        fTb, fgb + (long)NC8 * NTOK, sfg, attnb);

    // 5) out = gamma * (hvb @ attn) + x
    gemm_mma<2><<<dim3(NTOK / 128, NC / 128, BATCH), 256>>>(
        hvb, sx, NTOK, attnb, sat, NTOK, out, sx, NTOK,
        nullptr, x, sx, gamma, NTOK);
}